// round 8
// baseline (speedup 1.0000x reference)
#include <cuda_runtime.h>
#include <math.h>
#include <stdint.h>

// Problem constants
#define Bb 32
#define Tt 60
#define Ii 577
#define Hh 768
#define Pp 384
#define Gg 256
#define Cc 128
#define Nn 637    // Ii + Tt
#define NPAD 640  // Nn padded for guard-free K loop

// ---------------------------------------------------------------------------
// Rounded-input scratch segments (floats)
// ---------------------------------------------------------------------------
#define SZ_UTT_T  1474560
#define SZ_UTT_V  14177280
#define SZ_W      589824
#define SZ_WPROJ  294912
#define SZ_WG     98304
#define SZ_WC     32768
#define OFF_UTT_T 0
#define OFF_UTT_V (OFF_UTT_T + SZ_UTT_T)
#define OFF_WPT   (OFF_UTT_V + SZ_UTT_V)
#define OFF_WPV   (OFF_WPT + SZ_W)
#define OFF_WS    (OFF_WPV + SZ_W)
#define OFF_WPROJ (OFF_WS + SZ_W)
#define OFF_WG    (OFF_WPROJ + SZ_WPROJ)
#define OFF_WC    (OFF_WG + SZ_WG)
#define RND_TOTAL (OFF_WC + SZ_WC)

__device__ float g_rnd[RND_TOTAL];
__device__ float g_fcat[2][(size_t)Bb * Nn * Hh];
__device__ float g_x[2][(size_t)Bb * Nn * Pp];
__device__ float g_h[2][(size_t)Bb * Nn * Gg];
__device__ float g_gat[2][(size_t)Bb * Nn * Gg];
__device__ float g_el[2][Bb * Nn];
__device__ float g_er[2][Bb * Nn];
__device__ float g_iz[2][Bb * Nn];
__device__ float g_hgi[Bb * Pp];
__device__ float g_hgt[Bb * Pp];
__device__ float g_part[2 * Bb];

#define ACT_NONE 0
#define ACT_SIG  1
#define ACT_RELU 2
#define ACT_ELU  3
#define ACT_RND  4    // OR-flag: tf32-round stored output
#define ACT_GENP 8    // OR-flag: generate A-tile = softmax attention row

__device__ __forceinline__ float cvt_tf32(float x) {
    uint32_t u;
    asm("cvt.rna.tf32.f32 %0, %1;" : "=r"(u) : "f"(x));
    return __uint_as_float(u);
}

__device__ __forceinline__ void mma_tf32(float* c, const uint32_t* a, const uint32_t* b) {
    asm volatile(
        "mma.sync.aligned.m16n8k8.row.col.f32.tf32.tf32.f32 "
        "{%0,%1,%2,%3}, {%4,%5,%6,%7}, {%8,%9}, {%0,%1,%2,%3};"
        : "+f"(c[0]), "+f"(c[1]), "+f"(c[2]), "+f"(c[3])
        : "r"(a[0]), "r"(a[1]), "r"(a[2]), "r"(a[3]), "r"(b[0]), "r"(b[1]));
}

__device__ __forceinline__ void cp16(uint32_t dst, const void* src, bool pred) {
    int sz = pred ? 16 : 0;
    asm volatile("cp.async.cg.shared.global [%0], [%1], 16, %2;\n"
                 :: "r"(dst), "l"(src), "r"(sz));
}

// ---------------------------------------------------------------------------
// Multi-set TF32 GEMM, cp.async 3-stage pipeline (B side).
// 128x128x16 block, 256 threads (8 warps 2x4), warp tile 64x32, m16n8k8.
// Normal mode: A via cp.async (3 stages). GENP mode: A-tile generated in
// smem (2 stages) as P[d,s] = cvt_tf32(expf(lrelu(el[s]+er[d]))*invZ[d]),
// s != d, s < Kb. GSet.A = el base, GSet.bias = er base, GSet.iz = invZ base,
// all strided by sA per z. B = h via cp.async.
// ---------------------------------------------------------------------------
#define BM 128
#define BN 128
#define BK 16
#define LDA 20
#define LDB 136
#define STAGES 3
#define ASTAGE (BM * LDA)                        // 2560 floats
#define BSTAGE (BK * LDB)                        // 2176 floats
#define SM_FLOATS (STAGES * (ASTAGE + BSTAGE))   // 14208 floats
#define SM_TOTALF (SM_FLOATS + NPAD)             // + el buffer

struct GSet {
    const float* A; const float* B; const float* bias; float* C;
    const float* iz;
    int M; int rowsPer; int rowOff;
};
struct GArgs {
    GSet s[4];
    int zEnd[4];
    int nSets;
    int N, K, Kb, lda, ldb, ldc;
    long sA, sB, sC;
    int mode;
};

__global__ __launch_bounds__(256, 2) void mma_gemm(GArgs ga)
{
    int z = blockIdx.z;
    int si = 0;
    while (si < ga.nSets - 1 && z >= ga.zEnd[si]) si++;
    const int zStart = (si == 0) ? 0 : ga.zEnd[si - 1];
    const GSet st = ga.s[si];
    const int M = st.M;
    const int row0 = blockIdx.y * BM;
    if (row0 >= M) return;
    const long zi = z - zStart;
    const float* A  = st.A + zi * ga.sA;
    const float* Bm = st.B + zi * ga.sB;
    float*       C  = st.C + zi * ga.sC;

    const bool genp = (ga.mode & ACT_GENP) != 0;
    const int lda = ga.lda, ldb = ga.ldb, Kb = ga.Kb;
    const int col0 = blockIdx.x * BN;

    extern __shared__ float sm[];
    float* AsBase = sm;
    float* BsBase = sm + STAGES * ASTAGE;
    float* elsm   = sm + SM_FLOATS;
    const uint32_t smAddr = (uint32_t)__cvta_generic_to_shared(sm);

    const int tid  = threadIdx.x;
    const int lane = tid & 31;
    const int warp = tid >> 5;
    const int wr   = warp >> 2;
    const int wc   = warp & 3;
    const int g    = lane >> 2;
    const int tg   = lane & 3;

    const int ar = tid >> 1, ac = (tid & 1) * 8;
    const int br = tid >> 5, bc = (tid & 31) * 4;
    const bool pa = (row0 + ar) < M;
    const float* aSrc = A + (long)(row0 + (pa ? ar : 0)) * lda + ac;
    const float* bSrc = Bm + col0 + bc;

    const int nTiles = ga.K / BK;

    // GENP per-thread row constants + el staging
    float erd = 0.f, izd = 0.f;
    if (genp) {
        const float* erB = st.bias + zi * ga.sA;
        const float* izB = st.iz   + zi * ga.sA;
        int d = row0 + ar;
        int dc = pa ? d : 0;
        erd = erB[dc];
        izd = izB[dc];
        for (int i = tid; i < Kb; i += 256) elsm[i] = A[i];
        __syncthreads();
    }

    // A-tile generation (GENP): stage in {0,1}
    auto genA = [&](int stage, int kt) {
        const int k0 = kt * BK + ac;
        const int d  = row0 + ar;
        float* dst = AsBase + stage * ASTAGE + ar * LDA + ac;
        #pragma unroll
        for (int j = 0; j < 8; j++) {
            int s = k0 + j;
            float v = 0.f;
            if (s < Kb && s != d) {
                float x = elsm[s] + erd;
                x = x > 0.f ? x : 0.2f * x;
                v = cvt_tf32(__expf(x) * izd);
            }
            dst[j] = v;
        }
    };

    // prologue
    #pragma unroll
    for (int s = 0; s < STAGES - 1; s++) {
        const int k0 = s * BK;
        if (!genp) {
            uint32_t da = smAddr + (uint32_t)(s * ASTAGE + ar * LDA + ac) * 4;
            cp16(da,      aSrc + k0,     pa);
            cp16(da + 16, aSrc + k0 + 4, pa);
        }
        #pragma unroll
        for (int i = 0; i < 2; i++) {
            int k = br + i * 8;
            bool pb = (k0 + k) < Kb;
            uint32_t db = smAddr + (uint32_t)(STAGES * ASTAGE + s * BSTAGE + k * LDB + bc) * 4;
            cp16(db, bSrc + (long)(k0 + (pb ? k : 0)) * ldb, pb);
        }
        asm volatile("cp.async.commit_group;\n" ::: "memory");
    }
    if (genp) genA(0, 0);

    float acc[4][4][4] = {};

    for (int t = 0; t < nTiles; t++) {
        asm volatile("cp.async.wait_group 1;\n" ::: "memory");
        __syncthreads();

        const int aCur = genp ? (t & 1) : (t % STAGES);
        const float* As = AsBase + aCur * ASTAGE;
        const float* Bs = BsBase + (t % STAGES) * BSTAGE;

        #pragma unroll
        for (int ks = 0; ks < 2; ks++) {
            const int k0 = ks * 8;
            uint32_t bf[4][2];
            #pragma unroll
            for (int ni = 0; ni < 4; ni++) {
                int n = wc * 32 + ni * 8 + g;
                bf[ni][0] = __float_as_uint(Bs[(k0 + tg) * LDB + n]);
                bf[ni][1] = __float_as_uint(Bs[(k0 + 4 + tg) * LDB + n]);
            }
            #pragma unroll
            for (int mi = 0; mi < 4; mi++) {
                int m = wr * 64 + mi * 16 + g;
                uint32_t af[4];
                af[0] = __float_as_uint(As[m * LDA + k0 + tg]);
                af[1] = __float_as_uint(As[(m + 8) * LDA + k0 + tg]);
                af[2] = __float_as_uint(As[m * LDA + k0 + 4 + tg]);
                af[3] = __float_as_uint(As[(m + 8) * LDA + k0 + 4 + tg]);
                #pragma unroll
                for (int ni = 0; ni < 4; ni++)
                    mma_tf32(acc[mi][ni], af, bf[ni]);
            }
        }

        // next A tile
        if (genp) {
            if (t + 1 < nTiles) genA((t + 1) & 1, t + 1);
        }
        const int nt = t + STAGES - 1;
        if (nt < nTiles) {
            const int s = nt % STAGES;
            const int k0 = nt * BK;
            if (!genp) {
                uint32_t da = smAddr + (uint32_t)(s * ASTAGE + ar * LDA + ac) * 4;
                cp16(da,      aSrc + k0,     pa);
                cp16(da + 16, aSrc + k0 + 4, pa);
            }
            #pragma unroll
            for (int i = 0; i < 2; i++) {
                int k = br + i * 8;
                bool pb = (k0 + k) < Kb;
                uint32_t db = smAddr + (uint32_t)(STAGES * ASTAGE + s * BSTAGE + k * LDB + bc) * 4;
                cp16(db, bSrc + (long)(k0 + (pb ? k : 0)) * ldb, pb);
            }
        }
        asm volatile("cp.async.commit_group;\n" ::: "memory");
    }

    // epilogue
    const int act = ga.mode & 3;
    const bool rnd = (ga.mode & ACT_RND) != 0;
    const float* bias = genp ? nullptr : st.bias;
    #pragma unroll
    for (int mi = 0; mi < 4; mi++) {
        #pragma unroll
        for (int half = 0; half < 2; half++) {
            int r = row0 + wr * 64 + mi * 16 + g + half * 8;
            if (r >= M) continue;
            long orow = r;
            if (st.rowsPer > 0)
                orow = (long)(r / st.rowsPer) * Nn + st.rowOff + (r % st.rowsPer);
            float* cbase = C + orow * (long)ga.ldc;
            #pragma unroll
            for (int ni = 0; ni < 4; ni++) {
                int col = col0 + wc * 32 + ni * 8 + 2 * tg;
                float v0 = acc[mi][ni][half * 2 + 0];
                float v1 = acc[mi][ni][half * 2 + 1];
                if (bias) { v0 += bias[col]; v1 += bias[col + 1]; }
                if (act == ACT_SIG) {
                    v0 = 1.f / (1.f + expf(-v0));
                    v1 = 1.f / (1.f + expf(-v1));
                } else if (act == ACT_RELU) {
                    v0 = fmaxf(v0, 0.f); v1 = fmaxf(v1, 0.f);
                } else if (act == ACT_ELU) {
                    v0 = v0 > 0.f ? v0 : expm1f(v0);
                    v1 = v1 > 0.f ? v1 : expm1f(v1);
                }
                if (rnd) { v0 = cvt_tf32(v0); v1 = cvt_tf32(v1); }
                *(float2*)(cbase + col) = make_float2(v0, v1);
            }
        }
    }
}

// ---------------------------------------------------------------------------
// Pre-round inputs + weights to tf32 into g_rnd
// ---------------------------------------------------------------------------
struct RArgs { const float4* src[8]; };

__global__ void round_kernel(RArgs ra, float4* dst)
{
    const int seg[9] = {0, 368640, 3912960, 4060416, 4207872,
                        4355328, 4429056, 4453632, 4461824};
    const int total = 4461824;
    for (int i = blockIdx.x * blockDim.x + threadIdx.x; i < total;
         i += gridDim.x * blockDim.x) {
        int s = 0;
        while (i >= seg[s + 1]) s++;
        float4 v = ra.src[s][i - seg[s]];
        v.x = cvt_tf32(v.x); v.y = cvt_tf32(v.y);
        v.z = cvt_tf32(v.z); v.w = cvt_tf32(v.w);
        dst[i] = v;
    }
}

// ---------------------------------------------------------------------------
// Scores for both branches: grid.y = branch
// ---------------------------------------------------------------------------
__global__ void score_kernel(const float* __restrict__ h0,
                             const float* __restrict__ h1,
                             const float* __restrict__ al,
                             const float* __restrict__ ar,
                             float* __restrict__ el, float* __restrict__ er)
{
    int br = blockIdx.y;
    int row = blockIdx.x;
    const float* h = (br == 0) ? h0 : h1;
    const float* hr = h + (long)row * Gg;
    int t = threadIdx.x;   // 128
    float a = hr[t] * al[t] + hr[t + 128] * al[t + 128];
    float b = hr[t] * ar[t] + hr[t + 128] * ar[t + 128];
    __shared__ float sa[128], sb[128];
    sa[t] = a; sb[t] = b; __syncthreads();
    for (int o = 64; o > 0; o >>= 1) {
        if (t < o) { sa[t] += sa[t + o]; sb[t] += sb[t + o]; }
        __syncthreads();
    }
    if (t == 0) {
        el[br * (Bb * Nn) + row] = sa[0];
        er[br * (Bb * Nn) + row] = sb[0];
    }
}

// ---------------------------------------------------------------------------
// invZ per destination row, both branches: grid (Bb*Nn, 2), 256 threads
// ---------------------------------------------------------------------------
__global__ void z_kernel(const float* __restrict__ el,
                         const float* __restrict__ er,
                         float* __restrict__ iz)
{
    int brn = blockIdx.y;
    int row = blockIdx.x;              // b*Nn + d
    int b = row / Nn, d = row % Nn;
    const float* elb = el + brn * (Bb * Nn) + b * Nn;
    float erd = er[brn * (Bb * Nn) + row];
    int t = threadIdx.x;               // 256

    float s = 0.f;
    #pragma unroll
    for (int it = 0; it < 3; it++) {
        int sIdx = t + it * 256;
        if (sIdx < Nn && sIdx != d) {
            float x = elb[sIdx] + erd;
            x = x > 0.f ? x : 0.2f * x;
            s += __expf(x);
        }
    }
    __shared__ float red[256];
    red[t] = s; __syncthreads();
    for (int o = 128; o > 0; o >>= 1) {
        if (t < o) red[t] += red[t + o];
        __syncthreads();
    }
    if (t == 0) iz[brn * (Bb * Nn) + row] = 1.f / red[0];
}

// ---------------------------------------------------------------------------
// Column means, high-MLP: grid (Bb, Pp/128, 2), block (128, 4)
// ---------------------------------------------------------------------------
__global__ void mean_kernel(const float* __restrict__ x,
                            float* __restrict__ hgi, float* __restrict__ hgt)
{
    int which = blockIdx.z;
    int rowOff = which ? Ii : 0;
    int cnt    = which ? Tt : Ii;
    float* outp = which ? hgt : hgi;
    int b  = blockIdx.x;
    int tx = threadIdx.x;              // 128 p-lanes
    int rg = threadIdx.y;              // 4 row groups
    int p  = blockIdx.y * 128 + tx;
    const float* base = x + ((long)b * Nn + rowOff) * Pp + p;
    float s = 0.f;
    #pragma unroll 4
    for (int i = rg; i < cnt; i += 4) s += base[(long)i * Pp];
    __shared__ float red[4][128];
    red[rg][tx] = s;
    __syncthreads();
    if (rg == 0)
        outp[b * Pp + p] =
            (red[0][tx] + red[1][tx] + red[2][tx] + red[3][tx]) / (float)cnt;
}

// ---------------------------------------------------------------------------
// Symmetric KL partials per batch row (exact fp32 log-softmax)
// ---------------------------------------------------------------------------
__global__ void kl_kernel(const float* __restrict__ Pm, long sp,
                          const float* __restrict__ Qm, long sq,
                          int D, float* __restrict__ part)
{
    int b = blockIdx.x;
    const float* p = Pm + b * sp;
    const float* q = Qm + b * sq;
    int t = threadIdx.x;   // 128
    __shared__ float s1[128], s2[128];

    float mp = -1e30f, mq = -1e30f;
    for (int c = t; c < D; c += 128) { mp = fmaxf(mp, p[c]); mq = fmaxf(mq, q[c]); }
    s1[t] = mp; s2[t] = mq; __syncthreads();
    for (int o = 64; o > 0; o >>= 1) {
        if (t < o) { s1[t] = fmaxf(s1[t], s1[t + o]); s2[t] = fmaxf(s2[t], s2[t + o]); }
        __syncthreads();
    }
    float MP = s1[0], MQ = s2[0];
    __syncthreads();

    float ssp = 0.f, ssq = 0.f;
    for (int c = t; c < D; c += 128) { ssp += expf(p[c] - MP); ssq += expf(q[c] - MQ); }
    s1[t] = ssp; s2[t] = ssq; __syncthreads();
    for (int o = 64; o > 0; o >>= 1) {
        if (t < o) { s1[t] += s1[t + o]; s2[t] += s2[t + o]; }
        __syncthreads();
    }
    float lsep = MP + logf(s1[0]);
    float lseq = MQ + logf(s2[0]);
    __syncthreads();

    float kpq = 0.f, kqp = 0.f;
    for (int c = t; c < D; c += 128) {
        float lp = p[c] - lsep, lq = q[c] - lseq;
        kpq += expf(lq) * (lq - lp);
        kqp += expf(lp) * (lp - lq);
    }
    s1[t] = kpq; s2[t] = kqp; __syncthreads();
    for (int o = 64; o > 0; o >>= 1) {
        if (t < o) { s1[t] += s1[t + o]; s2[t] += s2[t + o]; }
        __syncthreads();
    }
    if (t == 0) { part[b] = s1[0]; part[Bb + b] = s2[0]; }
}

__global__ void kl_final(const float* __restrict__ part, float* __restrict__ out)
{
    int t = threadIdx.x;   // 32
    float a = part[t], b = part[Bb + t];
    for (int o = 16; o > 0; o >>= 1) {
        a += __shfl_down_sync(0xffffffff, a, o);
        b += __shfl_down_sync(0xffffffff, b, o);
    }
    if (t == 0) out[0] = 0.5f * (a + b);
}

// ---------------------------------------------------------------------------
// Host launch
// ---------------------------------------------------------------------------
extern "C" void kernel_launch(void* const* d_in, const int* in_sizes, int n_in,
                              void* d_out, int out_size)
{
    const float* utt_t = (const float*)d_in[0];
    const float* utt_v = (const float*)d_in[1];
    const float* Wpt   = (const float*)d_in[2];
    const float* bpt   = (const float*)d_in[3];
    const float* Wpv   = (const float*)d_in[4];
    const float* bpv   = (const float*)d_in[5];
    const float* Ws    = (const float*)d_in[6];
    const float* bs    = (const float*)d_in[7];
    const float* Wproj = (const float*)d_in[8];
    const float* bproj = (const float*)d_in[9];
    const float* Wg    = (const float*)d_in[10];
    const float* al    = (const float*)d_in[11];
    const float* ar    = (const float*)d_in[12];
    const float* Wc    = (const float*)d_in[13];
    const float* bc    = (const float*)d_in[14];
    float* out = (float*)d_out;

    float *rnd, *fcat0, *x0, *h0, *gat0, *el, *er, *iz, *hgi, *hgt, *part;
    cudaGetSymbolAddress((void**)&rnd,  g_rnd);
    cudaGetSymbolAddress((void**)&fcat0,g_fcat);
    cudaGetSymbolAddress((void**)&x0,   g_x);
    cudaGetSymbolAddress((void**)&h0,   g_h);
    cudaGetSymbolAddress((void**)&gat0, g_gat);
    cudaGetSymbolAddress((void**)&el,   g_el);
    cudaGetSymbolAddress((void**)&er,   g_er);
    cudaGetSymbolAddress((void**)&iz,   g_iz);
    cudaGetSymbolAddress((void**)&hgi,  g_hgi);
    cudaGetSymbolAddress((void**)&hgt,  g_hgt);
    cudaGetSymbolAddress((void**)&part, g_part);

    float* fcat1 = fcat0 + (size_t)Bb * Nn * Hh;
    float* x1    = x0    + (size_t)Bb * Nn * Pp;
    float* h1    = h0    + (size_t)Bb * Nn * Gg;
    float* gat1  = gat0  + (size_t)Bb * Nn * Gg;

    const float* utt_t_r = rnd + OFF_UTT_T;
    const float* utt_v_r = rnd + OFF_UTT_V;
    const float* Wpt_r   = rnd + OFF_WPT;
    const float* Wpv_r   = rnd + OFF_WPV;
    const float* Ws_r    = rnd + OFF_WS;
    const float* Wproj_r = rnd + OFF_WPROJ;
    const float* Wg_r    = rnd + OFF_WG;
    const float* Wc_r    = rnd + OFF_WC;

    const long EMB = (long)Bb * Nn * Cc;
    const size_t smemBytes = SM_TOTALF * sizeof(float);

    cudaFuncSetAttribute(mma_gemm,
        cudaFuncAttributeMaxDynamicSharedMemorySize, (int)smemBytes);

    // 0) pre-round inputs + weights
    {
        RArgs ra;
        ra.src[0] = (const float4*)utt_t; ra.src[1] = (const float4*)utt_v;
        ra.src[2] = (const float4*)Wpt;   ra.src[3] = (const float4*)Wpv;
        ra.src[4] = (const float4*)Ws;    ra.src[5] = (const float4*)Wproj;
        ra.src[6] = (const float4*)Wg;    ra.src[7] = (const float4*)Wc;
        round_kernel<<<2368, 256>>>(ra, (float4*)rnd);
    }

    // 1) fused sigmoid layer: 4 sets -> f_cat
    {
        GArgs ga = {};
        ga.s[0] = { utt_v_r, Wpv_r, bpv, fcat0, nullptr, Bb * Ii, Ii, 0 };
        ga.s[1] = { utt_v_r, Ws_r,  bs,  fcat1, nullptr, Bb * Ii, Ii, 0 };
        ga.s[2] = { utt_t_r, Wpt_r, bpt, fcat0, nullptr, Bb * Tt, Tt, Ii };
        ga.s[3] = { utt_t_r, Ws_r,  bs,  fcat1, nullptr, Bb * Tt, Tt, Ii };
        ga.zEnd[0] = 1; ga.zEnd[1] = 2; ga.zEnd[2] = 3; ga.zEnd[3] = 4;
        ga.nSets = 4;
        ga.N = Hh; ga.K = Hh; ga.Kb = Hh; ga.lda = Hh; ga.ldb = Hh; ga.ldc = Hh;
        ga.sA = ga.sB = ga.sC = 0;
        ga.mode = ACT_SIG | ACT_RND;
        dim3 grid(Hh / BN, (Bb * Ii + BM - 1) / BM, 4);
        mma_gemm<<<grid, 256, smemBytes>>>(ga);
    }

    // 2) relu projection: x = relu(f_cat @ Wproj + b)
    {
        GArgs ga = {};
        ga.s[0] = { fcat0, Wproj_r, bproj, x0, nullptr, Bb * Nn, 0, 0 };
        ga.s[1] = { fcat1, Wproj_r, bproj, x1, nullptr, Bb * Nn, 0, 0 };
        ga.zEnd[0] = 1; ga.zEnd[1] = 2; ga.nSets = 2;
        ga.N = Pp; ga.K = Hh; ga.Kb = Hh; ga.lda = Hh; ga.ldb = Pp; ga.ldc = Pp;
        ga.sA = ga.sB = ga.sC = 0;
        ga.mode = ACT_RELU | ACT_RND;
        dim3 grid(Pp / BN, (Bb * Nn + BM - 1) / BM, 2);
        mma_gemm<<<grid, 256, smemBytes>>>(ga);
    }

    // share-branch readout means (x1)
    mean_kernel<<<dim3(Bb, Pp / 128, 2), dim3(128, 4)>>>(x1, hgi, hgt);

    // 3) h = x @ Wg
    {
        GArgs ga = {};
        ga.s[0] = { x0, Wg_r, nullptr, h0, nullptr, Bb * Nn, 0, 0 };
        ga.s[1] = { x1, Wg_r, nullptr, h1, nullptr, Bb * Nn, 0, 0 };
        ga.zEnd[0] = 1; ga.zEnd[1] = 2; ga.nSets = 2;
        ga.N = Gg; ga.K = Pp; ga.Kb = Pp; ga.lda = Pp; ga.ldb = Gg; ga.ldc = Gg;
        ga.sA = ga.sB = ga.sC = 0;
        ga.mode = ACT_NONE | ACT_RND;
        dim3 grid(Gg / BN, (Bb * Nn + BM - 1) / BM, 2);
        mma_gemm<<<grid, 256, smemBytes>>>(ga);
    }

    // 4) scores + invZ
    score_kernel<<<dim3(Bb * Nn, 2), 128>>>(h0, h1, al, ar, el, er);
    z_kernel<<<dim3(Bb * Nn, 2), 256>>>(el, er, iz);

    // 5) gat = elu(P @ h) with P generated on the fly, batched 2*Bb samples
    {
        GArgs ga = {};
        ga.s[0] = { el,           h0, er,           gat0, iz,           Nn, 0, 0 };
        ga.s[1] = { el + Bb * Nn, h1, er + Bb * Nn, gat1, iz + Bb * Nn, Nn, 0, 0 };
        ga.zEnd[0] = Bb; ga.zEnd[1] = 2 * Bb; ga.nSets = 2;
        ga.N = Gg; ga.K = NPAD; ga.Kb = Nn;
        ga.lda = Nn; ga.ldb = Gg; ga.ldc = Gg;
        ga.sA = Nn; ga.sB = (long)Nn * Gg; ga.sC = (long)Nn * Gg;
        ga.mode = ACT_ELU | ACT_RND | ACT_GENP;
        dim3 grid(Gg / BN, (Nn + BM - 1) / BM, 2 * Bb);
        mma_gemm<<<grid, 256, smemBytes>>>(ga);
    }

    // 6) emb = gat @ Wc + bc -> final output (fp32)
    {
        GArgs ga = {};
        ga.s[0] = { gat0, Wc_r, bc, out,       nullptr, Bb * Nn, 0, 0 };
        ga.s[1] = { gat1, Wc_r, bc, out + EMB, nullptr, Bb * Nn, 0, 0 };
        ga.zEnd[0] = 1; ga.zEnd[1] = 2; ga.nSets = 2;
        ga.N = Cc; ga.K = Gg; ga.Kb = Gg; ga.lda = Gg; ga.ldb = Cc; ga.ldc = Cc;
        ga.sA = ga.sB = ga.sC = 0;
        ga.mode = ACT_NONE;
        dim3 grid(Cc / BN, (Bb * Nn + BM - 1) / BM, 2);
        mma_gemm<<<grid, 256, smemBytes>>>(ga);
    }

    // losses
    kl_kernel<<<Bb, 128>>>(hgi, (long)Pp, hgt, (long)Pp, Pp, part);
    kl_final<<<1, 32>>>(part, out + 2 * EMB);
    kl_kernel<<<Bb, 128>>>(out + EMB, (long)Nn * Cc, out, (long)Nn * Cc, Cc, part);
    kl_final<<<1, 32>>>(part, out + 2 * EMB + 1);
}

// round 9
// speedup vs baseline: 1.1157x; 1.1157x over previous
#include <cuda_runtime.h>
#include <math.h>
#include <stdint.h>

// Problem constants
#define Bb 32
#define Tt 60
#define Ii 577
#define Hh 768
#define Pp 384
#define Gg 256
#define Cc 128
#define Nn 637    // Ii + Tt
#define NPAD 640  // Nn padded for guard-free K loop

// ---------------------------------------------------------------------------
// Rounded-input scratch segments (floats)
// ---------------------------------------------------------------------------
#define SZ_UTT_T  1474560    // 32*60*768
#define SZ_UTT_V  14177280   // 32*577*768
#define SZ_W      589824     // 768*768
#define SZ_WPROJ  294912     // 768*384
#define SZ_WG     98304      // 384*256
#define SZ_WC     32768      // 256*128
#define OFF_UTT_T 0
#define OFF_UTT_V (OFF_UTT_T + SZ_UTT_T)
#define OFF_WPT   (OFF_UTT_V + SZ_UTT_V)
#define OFF_WPV   (OFF_WPT + SZ_W)
#define OFF_WS    (OFF_WPV + SZ_W)
#define OFF_WPROJ (OFF_WS + SZ_W)
#define OFF_WG    (OFF_WPROJ + SZ_WPROJ)
#define OFF_WC    (OFF_WG + SZ_WG)
#define RND_TOTAL (OFF_WC + SZ_WC)

__device__ float g_rnd[RND_TOTAL];
__device__ float g_fcat[2][(size_t)Bb * Nn * Hh];
__device__ float g_x[2][(size_t)Bb * Nn * Pp];
__device__ float g_h[2][(size_t)Bb * Nn * Gg];
__device__ float g_gat[2][(size_t)Bb * Nn * Gg];
__device__ float g_Pmat[2][(size_t)Bb * Nn * NPAD];
__device__ float g_el[2][Bb * Nn];
__device__ float g_er[2][Bb * Nn];
__device__ float g_hgi[Bb * Pp];
__device__ float g_hgt[Bb * Pp];
__device__ float g_part[2 * Bb];

#define ACT_NONE 0
#define ACT_SIG  1
#define ACT_RELU 2
#define ACT_ELU  3
#define ACT_RND  4   // OR-flag: tf32-round stored output

__device__ __forceinline__ float cvt_tf32(float x) {
    uint32_t u;
    asm("cvt.rna.tf32.f32 %0, %1;" : "=r"(u) : "f"(x));
    return __uint_as_float(u);
}

__device__ __forceinline__ void mma_tf32(float* c, const uint32_t* a, const uint32_t* b) {
    asm volatile(
        "mma.sync.aligned.m16n8k8.row.col.f32.tf32.tf32.f32 "
        "{%0,%1,%2,%3}, {%4,%5,%6,%7}, {%8,%9}, {%0,%1,%2,%3};"
        : "+f"(c[0]), "+f"(c[1]), "+f"(c[2]), "+f"(c[3])
        : "r"(a[0]), "r"(a[1]), "r"(a[2]), "r"(a[3]), "r"(b[0]), "r"(b[1]));
}

__device__ __forceinline__ void cp16(uint32_t dst, const void* src, bool pred) {
    int sz = pred ? 16 : 0;
    asm volatile("cp.async.cg.shared.global [%0], [%1], 16, %2;\n"
                 :: "r"(dst), "l"(src), "r"(sz));
}

// ---------------------------------------------------------------------------
// Multi-set TF32 GEMM, cp.async 4-stage pipeline.
// 128x128x16 block, 256 threads (8 warps 2x4), warp tile 64x32, m16n8k8.
// Up to 4 pointer sets selected by blockIdx.z ranges (zEnd cumulative).
// All inputs must be pre-rounded to tf32. K % 16 == 0, N % 128 == 0.
// Kb: B rows in [Kb, K) read as zero. Per-set M with row guard + early exit.
// rowsPer > 0 remaps output row r -> (r/rowsPer)*Nn + rowOff + r%rowsPer.
// ---------------------------------------------------------------------------
#define BM 128
#define BN 128
#define BK 16
#define LDA 20
#define LDB 136
#define STAGES 4
#define ASTAGE (BM * LDA)                        // 2560 floats
#define BSTAGE (BK * LDB)                        // 2176 floats
#define SM_FLOATS (STAGES * (ASTAGE + BSTAGE))   // 18944 floats = 75776 B

struct GSet {
    const float* A; const float* B; const float* bias; float* C;
    int M; int rowsPer; int rowOff;
};
struct GArgs {
    GSet s[4];
    int zEnd[4];
    int nSets;
    int N, K, Kb, lda, ldb, ldc;
    long sA, sB, sC;
    int mode;
};

__global__ __launch_bounds__(256, 2) void mma_gemm(GArgs ga)
{
    // resolve pointer set from z
    int z = blockIdx.z;
    int si = 0;
    while (si < ga.nSets - 1 && z >= ga.zEnd[si]) si++;
    const int zStart = (si == 0) ? 0 : ga.zEnd[si - 1];
    const GSet st = ga.s[si];
    const int M = st.M;
    const int row0 = blockIdx.y * BM;
    if (row0 >= M) return;                 // uniform early exit (unused tile)
    const long zi = z - zStart;
    const float* A  = st.A + zi * ga.sA;
    const float* Bm = st.B + zi * ga.sB;
    float*       C  = st.C + zi * ga.sC;

    const int lda = ga.lda, ldb = ga.ldb, Kb = ga.Kb;
    const int col0 = blockIdx.x * BN;

    extern __shared__ float sm[];
    float* AsBase = sm;
    float* BsBase = sm + STAGES * ASTAGE;
    const uint32_t smAddr = (uint32_t)__cvta_generic_to_shared(sm);

    const int tid  = threadIdx.x;
    const int lane = tid & 31;
    const int warp = tid >> 5;
    const int wr   = warp >> 2;
    const int wc   = warp & 3;
    const int g    = lane >> 2;
    const int tg   = lane & 3;

    // loader lane mapping
    const int ar = tid >> 1, ac = (tid & 1) * 8;   // A: row, 8-float col group
    const int br = tid >> 5, bc = (tid & 31) * 4;  // B: k-row, 4-float col group
    const bool pa = (row0 + ar) < M;
    const float* aSrc = A + (long)(row0 + (pa ? ar : 0)) * lda + ac;
    const float* bSrc = Bm + col0 + bc;

    const int nTiles = ga.K / BK;

    // prologue: stages 0..STAGES-2
    #pragma unroll
    for (int s = 0; s < STAGES - 1; s++) {
        const int k0 = s * BK;
        if (s < nTiles) {
            uint32_t da = smAddr + (uint32_t)(s * ASTAGE + ar * LDA + ac) * 4;
            cp16(da,      aSrc + k0,     pa);
            cp16(da + 16, aSrc + k0 + 4, pa);
            #pragma unroll
            for (int i = 0; i < 2; i++) {
                int k = br + i * 8;
                bool pb = (k0 + k) < Kb;
                uint32_t db = smAddr + (uint32_t)(STAGES * ASTAGE + s * BSTAGE + k * LDB + bc) * 4;
                cp16(db, bSrc + (long)(k0 + (pb ? k : 0)) * ldb, pb);
            }
        }
        asm volatile("cp.async.commit_group;\n" ::: "memory");
    }

    float acc[4][4][4] = {};

    for (int t = 0; t < nTiles; t++) {
        asm volatile("cp.async.wait_group 2;\n" ::: "memory");
        __syncthreads();

        const int cur = t % STAGES;
        const float* As = AsBase + cur * ASTAGE;
        const float* Bs = BsBase + cur * BSTAGE;

        #pragma unroll
        for (int ks = 0; ks < 2; ks++) {
            const int k0 = ks * 8;
            uint32_t bf[4][2];
            #pragma unroll
            for (int ni = 0; ni < 4; ni++) {
                int n = wc * 32 + ni * 8 + g;
                bf[ni][0] = __float_as_uint(Bs[(k0 + tg) * LDB + n]);
                bf[ni][1] = __float_as_uint(Bs[(k0 + 4 + tg) * LDB + n]);
            }
            #pragma unroll
            for (int mi = 0; mi < 4; mi++) {
                int m = wr * 64 + mi * 16 + g;
                uint32_t af[4];
                af[0] = __float_as_uint(As[m * LDA + k0 + tg]);
                af[1] = __float_as_uint(As[(m + 8) * LDA + k0 + tg]);
                af[2] = __float_as_uint(As[m * LDA + k0 + 4 + tg]);
                af[3] = __float_as_uint(As[(m + 8) * LDA + k0 + 4 + tg]);
                #pragma unroll
                for (int ni = 0; ni < 4; ni++)
                    mma_tf32(acc[mi][ni], af, bf[ni]);
            }
        }

        // issue load for tile t+STAGES-1 into its stage (read last at iter
        // t-1; every warp passed the sync above, so the write is safe)
        const int nt = t + STAGES - 1;
        if (nt < nTiles) {
            const int s = nt % STAGES;
            const int k0 = nt * BK;
            uint32_t da = smAddr + (uint32_t)(s * ASTAGE + ar * LDA + ac) * 4;
            cp16(da,      aSrc + k0,     pa);
            cp16(da + 16, aSrc + k0 + 4, pa);
            #pragma unroll
            for (int i = 0; i < 2; i++) {
                int k = br + i * 8;
                bool pb = (k0 + k) < Kb;
                uint32_t db = smAddr + (uint32_t)(STAGES * ASTAGE + s * BSTAGE + k * LDB + bc) * 4;
                cp16(db, bSrc + (long)(k0 + (pb ? k : 0)) * ldb, pb);
            }
        }
        asm volatile("cp.async.commit_group;\n" ::: "memory");
    }

    // epilogue
    const int act = ga.mode & 3;
    const bool rnd = (ga.mode & ACT_RND) != 0;
    const float* bias = st.bias;
    #pragma unroll
    for (int mi = 0; mi < 4; mi++) {
        #pragma unroll
        for (int half = 0; half < 2; half++) {
            int r = row0 + wr * 64 + mi * 16 + g + half * 8;
            if (r >= M) continue;
            long orow = r;
            if (st.rowsPer > 0)
                orow = (long)(r / st.rowsPer) * Nn + st.rowOff + (r % st.rowsPer);
            float* cbase = C + orow * (long)ga.ldc;
            #pragma unroll
            for (int ni = 0; ni < 4; ni++) {
                int col = col0 + wc * 32 + ni * 8 + 2 * tg;
                float v0 = acc[mi][ni][half * 2 + 0];
                float v1 = acc[mi][ni][half * 2 + 1];
                if (bias) { v0 += bias[col]; v1 += bias[col + 1]; }
                if (act == ACT_SIG) {
                    v0 = 1.f / (1.f + expf(-v0));
                    v1 = 1.f / (1.f + expf(-v1));
                } else if (act == ACT_RELU) {
                    v0 = fmaxf(v0, 0.f); v1 = fmaxf(v1, 0.f);
                } else if (act == ACT_ELU) {
                    v0 = v0 > 0.f ? v0 : expm1f(v0);
                    v1 = v1 > 0.f ? v1 : expm1f(v1);
                }
                if (rnd) { v0 = cvt_tf32(v0); v1 = cvt_tf32(v1); }
                *(float2*)(cbase + col) = make_float2(v0, v1);
            }
        }
    }
}

// ---------------------------------------------------------------------------
// Pre-round inputs + weights to tf32 into g_rnd (float4 grid-stride)
// ---------------------------------------------------------------------------
struct RArgs { const float4* src[8]; };

__global__ void round_kernel(RArgs ra, float4* dst)
{
    const int seg[9] = {0, 368640, 3912960, 4060416, 4207872,
                        4355328, 4429056, 4453632, 4461824};
    const int total = 4461824;
    for (int i = blockIdx.x * blockDim.x + threadIdx.x; i < total;
         i += gridDim.x * blockDim.x) {
        int s = 0;
        while (i >= seg[s + 1]) s++;
        float4 v = ra.src[s][i - seg[s]];
        v.x = cvt_tf32(v.x); v.y = cvt_tf32(v.y);
        v.z = cvt_tf32(v.z); v.w = cvt_tf32(v.w);
        dst[i] = v;
    }
}

// ---------------------------------------------------------------------------
// Scores for both branches: grid.y = branch
// ---------------------------------------------------------------------------
__global__ void score_kernel(const float* __restrict__ h0,
                             const float* __restrict__ h1,
                             const float* __restrict__ al,
                             const float* __restrict__ ar,
                             float* __restrict__ el, float* __restrict__ er)
{
    int br = blockIdx.y;
    int row = blockIdx.x;
    const float* h = (br == 0) ? h0 : h1;
    const float* hr = h + (long)row * Gg;
    int t = threadIdx.x;   // 128
    float a = hr[t] * al[t] + hr[t + 128] * al[t + 128];
    float b = hr[t] * ar[t] + hr[t + 128] * ar[t + 128];
    __shared__ float sa[128], sb[128];
    sa[t] = a; sb[t] = b; __syncthreads();
    for (int o = 64; o > 0; o >>= 1) {
        if (t < o) { sa[t] += sa[t + o]; sb[t] += sb[t + o]; }
        __syncthreads();
    }
    if (t == 0) {
        el[br * (Bb * Nn) + row] = sa[0];
        er[br * (Bb * Nn) + row] = sb[0];
    }
}

// ---------------------------------------------------------------------------
// Build normalized attention matrices (tf32-rounded) for both branches
// ---------------------------------------------------------------------------
__global__ void build_p_kernel(const float* __restrict__ el,
                               const float* __restrict__ er,
                               float* __restrict__ P0, float* __restrict__ P1)
{
    int brn = blockIdx.y;
    int row = blockIdx.x;              // b*Nn + d
    int b = row / Nn, d = row % Nn;
    const float* elb = el + brn * (Bb * Nn) + b * Nn;
    float erd = er[brn * (Bb * Nn) + row];
    float* pr = ((brn == 0) ? P0 : P1) + (long)row * NPAD;
    int t = threadIdx.x;               // 256

    float vals[3];
    float s = 0.f;
    #pragma unroll
    for (int it = 0; it < 3; it++) {
        int sIdx = t + it * 256;
        float v = 0.f;
        if (sIdx < Nn && sIdx != d) {
            float x = elb[sIdx] + erd;
            x = x > 0.f ? x : 0.2f * x;
            v = __expf(x);
        }
        vals[it] = v;
        s += v;
    }
    __shared__ float red[256];
    red[t] = s; __syncthreads();
    for (int o = 128; o > 0; o >>= 1) {
        if (t < o) red[t] += red[t + o];
        __syncthreads();
    }
    float inv = 1.f / red[0];
    #pragma unroll
    for (int it = 0; it < 3; it++) {
        int sIdx = t + it * 256;
        if (sIdx < NPAD) pr[sIdx] = cvt_tf32(vals[it] * inv);
    }
}

// ---------------------------------------------------------------------------
// Column means, high-MLP: grid (Bb, Pp/128, 2), block (128, 4)
// ---------------------------------------------------------------------------
__global__ void mean_kernel(const float* __restrict__ x,
                            float* __restrict__ hgi, float* __restrict__ hgt)
{
    int which = blockIdx.z;
    int rowOff = which ? Ii : 0;
    int cnt    = which ? Tt : Ii;
    float* outp = which ? hgt : hgi;
    int b  = blockIdx.x;
    int tx = threadIdx.x;              // 128 p-lanes
    int rg = threadIdx.y;              // 4 row groups
    int p  = blockIdx.y * 128 + tx;
    const float* base = x + ((long)b * Nn + rowOff) * Pp + p;
    float s = 0.f;
    #pragma unroll 4
    for (int i = rg; i < cnt; i += 4) s += base[(long)i * Pp];
    __shared__ float red[4][128];
    red[rg][tx] = s;
    __syncthreads();
    if (rg == 0)
        outp[b * Pp + p] =
            (red[0][tx] + red[1][tx] + red[2][tx] + red[3][tx]) / (float)cnt;
}

// ---------------------------------------------------------------------------
// Symmetric KL partials per batch row (exact fp32 log-softmax)
// ---------------------------------------------------------------------------
__global__ void kl_kernel(const float* __restrict__ Pm, long sp,
                          const float* __restrict__ Qm, long sq,
                          int D, float* __restrict__ part)
{
    int b = blockIdx.x;
    const float* p = Pm + b * sp;
    const float* q = Qm + b * sq;
    int t = threadIdx.x;   // 128
    __shared__ float s1[128], s2[128];

    float mp = -1e30f, mq = -1e30f;
    for (int c = t; c < D; c += 128) { mp = fmaxf(mp, p[c]); mq = fmaxf(mq, q[c]); }
    s1[t] = mp; s2[t] = mq; __syncthreads();
    for (int o = 64; o > 0; o >>= 1) {
        if (t < o) { s1[t] = fmaxf(s1[t], s1[t + o]); s2[t] = fmaxf(s2[t], s2[t + o]); }
        __syncthreads();
    }
    float MP = s1[0], MQ = s2[0];
    __syncthreads();

    float ssp = 0.f, ssq = 0.f;
    for (int c = t; c < D; c += 128) { ssp += expf(p[c] - MP); ssq += expf(q[c] - MQ); }
    s1[t] = ssp; s2[t] = ssq; __syncthreads();
    for (int o = 64; o > 0; o >>= 1) {
        if (t < o) { s1[t] += s1[t + o]; s2[t] += s2[t + o]; }
        __syncthreads();
    }
    float lsep = MP + logf(s1[0]);
    float lseq = MQ + logf(s2[0]);
    __syncthreads();

    float kpq = 0.f, kqp = 0.f;
    for (int c = t; c < D; c += 128) {
        float lp = p[c] - lsep, lq = q[c] - lseq;
        kpq += expf(lq) * (lq - lp);
        kqp += expf(lp) * (lp - lq);
    }
    s1[t] = kpq; s2[t] = kqp; __syncthreads();
    for (int o = 64; o > 0; o >>= 1) {
        if (t < o) { s1[t] += s1[t + o]; s2[t] += s2[t + o]; }
        __syncthreads();
    }
    if (t == 0) { part[b] = s1[0]; part[Bb + b] = s2[0]; }
}

__global__ void kl_final(const float* __restrict__ part, float* __restrict__ out)
{
    int t = threadIdx.x;   // 32
    float a = part[t], b = part[Bb + t];
    for (int o = 16; o > 0; o >>= 1) {
        a += __shfl_down_sync(0xffffffff, a, o);
        b += __shfl_down_sync(0xffffffff, b, o);
    }
    if (t == 0) out[0] = 0.5f * (a + b);
}

// ---------------------------------------------------------------------------
// Host launch
// ---------------------------------------------------------------------------
extern "C" void kernel_launch(void* const* d_in, const int* in_sizes, int n_in,
                              void* d_out, int out_size)
{
    const float* utt_t = (const float*)d_in[0];
    const float* utt_v = (const float*)d_in[1];
    const float* Wpt   = (const float*)d_in[2];
    const float* bpt   = (const float*)d_in[3];
    const float* Wpv   = (const float*)d_in[4];
    const float* bpv   = (const float*)d_in[5];
    const float* Ws    = (const float*)d_in[6];
    const float* bs    = (const float*)d_in[7];
    const float* Wproj = (const float*)d_in[8];
    const float* bproj = (const float*)d_in[9];
    const float* Wg    = (const float*)d_in[10];
    const float* al    = (const float*)d_in[11];
    const float* ar    = (const float*)d_in[12];
    const float* Wc    = (const float*)d_in[13];
    const float* bc    = (const float*)d_in[14];
    float* out = (float*)d_out;

    float *rnd, *fcat0, *x0, *h0, *gat0, *Pm0, *el, *er, *hgi, *hgt, *part;
    cudaGetSymbolAddress((void**)&rnd,  g_rnd);
    cudaGetSymbolAddress((void**)&fcat0,g_fcat);
    cudaGetSymbolAddress((void**)&x0,   g_x);
    cudaGetSymbolAddress((void**)&h0,   g_h);
    cudaGetSymbolAddress((void**)&gat0, g_gat);
    cudaGetSymbolAddress((void**)&Pm0,  g_Pmat);
    cudaGetSymbolAddress((void**)&el,   g_el);
    cudaGetSymbolAddress((void**)&er,   g_er);
    cudaGetSymbolAddress((void**)&hgi,  g_hgi);
    cudaGetSymbolAddress((void**)&hgt,  g_hgt);
    cudaGetSymbolAddress((void**)&part, g_part);

    float* fcat1 = fcat0 + (size_t)Bb * Nn * Hh;
    float* x1    = x0    + (size_t)Bb * Nn * Pp;
    float* h1    = h0    + (size_t)Bb * Nn * Gg;
    float* gat1  = gat0  + (size_t)Bb * Nn * Gg;
    float* Pm1   = Pm0   + (size_t)Bb * Nn * NPAD;

    const float* utt_t_r = rnd + OFF_UTT_T;
    const float* utt_v_r = rnd + OFF_UTT_V;
    const float* Wpt_r   = rnd + OFF_WPT;
    const float* Wpv_r   = rnd + OFF_WPV;
    const float* Ws_r    = rnd + OFF_WS;
    const float* Wproj_r = rnd + OFF_WPROJ;
    const float* Wg_r    = rnd + OFF_WG;
    const float* Wc_r    = rnd + OFF_WC;

    const long EMB = (long)Bb * Nn * Cc;
    const size_t smemBytes = SM_FLOATS * sizeof(float);   // 75776

    cudaFuncSetAttribute(mma_gemm,
        cudaFuncAttributeMaxDynamicSharedMemorySize, (int)smemBytes);

    // 0) pre-round inputs + weights
    {
        RArgs ra;
        ra.src[0] = (const float4*)utt_t; ra.src[1] = (const float4*)utt_v;
        ra.src[2] = (const float4*)Wpt;   ra.src[3] = (const float4*)Wpv;
        ra.src[4] = (const float4*)Ws;    ra.src[5] = (const float4*)Wproj;
        ra.src[6] = (const float4*)Wg;    ra.src[7] = (const float4*)Wc;
        round_kernel<<<2368, 256>>>(ra, (float4*)rnd);
    }

    // 1) fused sigmoid layer: 4 sets -> f_cat (v rows [0,Ii), t rows [Ii,Nn))
    {
        GArgs ga = {};
        ga.s[0] = { utt_v_r, Wpv_r, bpv, fcat0, Bb * Ii, Ii, 0 };
        ga.s[1] = { utt_v_r, Ws_r,  bs,  fcat1, Bb * Ii, Ii, 0 };
        ga.s[2] = { utt_t_r, Wpt_r, bpt, fcat0, Bb * Tt, Tt, Ii };
        ga.s[3] = { utt_t_r, Ws_r,  bs,  fcat1, Bb * Tt, Tt, Ii };
        ga.zEnd[0] = 1; ga.zEnd[1] = 2; ga.zEnd[2] = 3; ga.zEnd[3] = 4;
        ga.nSets = 4;
        ga.N = Hh; ga.K = Hh; ga.Kb = Hh; ga.lda = Hh; ga.ldb = Hh; ga.ldc = Hh;
        ga.sA = ga.sB = ga.sC = 0;
        ga.mode = ACT_SIG | ACT_RND;
        dim3 grid(Hh / BN, (Bb * Ii + BM - 1) / BM, 4);
        mma_gemm<<<grid, 256, smemBytes>>>(ga);
    }

    // 2) relu projection on concatenated rows: x = relu(f_cat @ Wproj + b)
    {
        GArgs ga = {};
        ga.s[0] = { fcat0, Wproj_r, bproj, x0, Bb * Nn, 0, 0 };
        ga.s[1] = { fcat1, Wproj_r, bproj, x1, Bb * Nn, 0, 0 };
        ga.zEnd[0] = 1; ga.zEnd[1] = 2; ga.nSets = 2;
        ga.N = Pp; ga.K = Hh; ga.Kb = Hh; ga.lda = Hh; ga.ldb = Pp; ga.ldc = Pp;
        ga.sA = ga.sB = ga.sC = 0;
        ga.mode = ACT_RELU | ACT_RND;
        dim3 grid(Pp / BN, (Bb * Nn + BM - 1) / BM, 2);
        mma_gemm<<<grid, 256, smemBytes>>>(ga);
    }

    // share-branch readout means (x1)
    mean_kernel<<<dim3(Bb, Pp / 128, 2), dim3(128, 4)>>>(x1, hgi, hgt);

    // 3) h = x @ Wg
    {
        GArgs ga = {};
        ga.s[0] = { x0, Wg_r, nullptr, h0, Bb * Nn, 0, 0 };
        ga.s[1] = { x1, Wg_r, nullptr, h1, Bb * Nn, 0, 0 };
        ga.zEnd[0] = 1; ga.zEnd[1] = 2; ga.nSets = 2;
        ga.N = Gg; ga.K = Pp; ga.Kb = Pp; ga.lda = Pp; ga.ldb = Gg; ga.ldc = Gg;
        ga.sA = ga.sB = ga.sC = 0;
        ga.mode = ACT_NONE | ACT_RND;
        dim3 grid(Gg / BN, (Bb * Nn + BM - 1) / BM, 2);
        mma_gemm<<<grid, 256, smemBytes>>>(ga);
    }

    // 4) scores + 5) attention matrices (both branches)
    score_kernel<<<dim3(Bb * Nn, 2), 128>>>(h0, h1, al, ar, el, er);
    build_p_kernel<<<dim3(Bb * Nn, 2), 256>>>(el, er, Pm0, Pm1);

    // 6) gat = elu(P @ h), batched 2*Bb samples
    {
        GArgs ga = {};
        ga.s[0] = { Pm0, h0, nullptr, gat0, Nn, 0, 0 };
        ga.s[1] = { Pm1, h1, nullptr, gat1, Nn, 0, 0 };
        ga.zEnd[0] = Bb; ga.zEnd[1] = 2 * Bb; ga.nSets = 2;
        ga.N = Gg; ga.K = NPAD; ga.Kb = Nn;
        ga.lda = NPAD; ga.ldb = Gg; ga.ldc = Gg;
        ga.sA = (long)Nn * NPAD; ga.sB = (long)Nn * Gg; ga.sC = (long)Nn * Gg;
        ga.mode = ACT_ELU | ACT_RND;
        dim3 grid(Gg / BN, (Nn + BM - 1) / BM, 2 * Bb);
        mma_gemm<<<grid, 256, smemBytes>>>(ga);
    }

    // 7) emb = gat @ Wc + bc -> final output (fp32, no rounding)
    {
        GArgs ga = {};
        ga.s[0] = { gat0, Wc_r, bc, out,       Bb * Nn, 0, 0 };
        ga.s[1] = { gat1, Wc_r, bc, out + EMB, Bb * Nn, 0, 0 };
        ga.zEnd[0] = 1; ga.zEnd[1] = 2; ga.nSets = 2;
        ga.N = Cc; ga.K = Gg; ga.Kb = Gg; ga.lda = Gg; ga.ldb = Cc; ga.ldc = Cc;
        ga.sA = ga.sB = ga.sC = 0;
        ga.mode = ACT_NONE;
        dim3 grid(Cc / BN, (Bb * Nn + BM - 1) / BM, 2);
        mma_gemm<<<grid, 256, smemBytes>>>(ga);
    }

    // losses
    kl_kernel<<<Bb, 128>>>(hgi, (long)Pp, hgt, (long)Pp, Pp, part);
    kl_final<<<1, 32>>>(part, out + 2 * EMB);
    kl_kernel<<<Bb, 128>>>(out + EMB, (long)Nn * Cc, out, (long)Nn * Cc, Cc, part);
    kl_final<<<1, 32>>>(part, out + 2 * EMB + 1);
}